// round 1
// baseline (speedup 1.0000x reference)
#include <cuda_runtime.h>

// Problem constants
#define BB   8
#define C    256
#define HH   64
#define WW   64
#define K2   9
#define COUT 256
#define PLANE (HH*WW)      // 4096
#define NPIX  (BB*PLANE)   // 32768

// GEMM tiling
#define BM 128
#define BN 64
#define BK 8

// Scratch (static device allocations; no cudaMalloc allowed)
__device__ float g_wt[K2*C*COUT];          // weight transposed: [(k*C + c)*COUT + o]
__device__ float g_mw0[BB*K2*PLANE];
__device__ float g_mw1[BB*K2*PLANE];
__device__ float g_mw2[BB*K2*PLANE];
__device__ float g_mw3[BB*K2*PLANE];
__device__ int   g_mi0[BB*K2*PLANE];
__device__ int   g_mi1[BB*K2*PLANE];
__device__ int   g_mi2[BB*K2*PLANE];
__device__ int   g_mi3[BB*K2*PLANE];

// ---------------------------------------------------------------------------
// Kernel 1: transpose weight [o][c][k] -> [(k*C + c)*COUT + o]
// ---------------------------------------------------------------------------
__global__ void wtranspose_kernel(const float* __restrict__ w) {
    int idx = blockIdx.x * 256 + threadIdx.x;
    if (idx >= K2*C*COUT) return;
    int o  = idx & 255;
    int kc = idx >> 8;          // k*C + c   (C == 256)
    int c  = kc & 255;
    int k  = kc >> 8;
    g_wt[idx] = w[(o*C + c)*K2 + k];
}

// ---------------------------------------------------------------------------
// Kernel 2: per-(b,k,pixel) bilinear metadata: 4 weights + 4 clamped indices
// ---------------------------------------------------------------------------
__global__ void meta_kernel(const float* __restrict__ off) {
    int e = blockIdx.x * 256 + threadIdx.x;
    if (e >= BB*K2*PLANE) return;
    int p  = e & (PLANE - 1);
    int bk = e >> 12;
    int k  = bk % 9;
    int b  = bk / 9;
    int ho = p >> 6;
    int wo = p & 63;

    float dy = off[((size_t)(b*18 + 2*k    ) << 12) + p];
    float dx = off[((size_t)(b*18 + 2*k + 1) << 12) + p];

    float py = (float)(ho - 1 + (k / 3)) + dy;   // STRIDE=1, PAD=1, DIL=1
    float px = (float)(wo - 1 + (k % 3)) + dx;

    float y0f = floorf(py), x0f = floorf(px);
    float fy = py - y0f, fx = px - x0f;
    int   y0 = (int)y0f,  x0 = (int)x0f;

    float wy[2] = {1.0f - fy, fy};
    float wx[2] = {1.0f - fx, fx};
    int   ys[2] = {y0, y0 + 1};
    int   xs[2] = {x0, x0 + 1};

    float mw[4]; int mi[4];
    #pragma unroll
    for (int jy = 0; jy < 2; jy++) {
        #pragma unroll
        for (int jx = 0; jx < 2; jx++) {
            int j = jy*2 + jx;
            int cy = ys[jy], cx = xs[jx];
            bool valid = (cy >= 0) && (cy < HH) && (cx >= 0) && (cx < WW);
            float wgt = valid ? wy[jy] * wx[jx] : 0.0f;
            int iy = min(max(cy, 0), HH - 1);
            int ix = min(max(cx, 0), WW - 1);
            mw[j] = wgt;
            mi[j] = iy * WW + ix;
        }
    }
    g_mw0[e] = mw[0]; g_mw1[e] = mw[1]; g_mw2[e] = mw[2]; g_mw3[e] = mw[3];
    g_mi0[e] = mi[0]; g_mi1[e] = mi[1]; g_mi2[e] = mi[2]; g_mi3[e] = mi[3];
}

// ---------------------------------------------------------------------------
// Kernel 3: fused im2col + GEMM
//   grid.x = pixel tile (one (b,ho) row of 64 pixels),  grid.y = Cout tile
//   256 threads, BM=128 x BN=64 tile, BK=8, 8x4 microtile per thread
// ---------------------------------------------------------------------------
__global__ __launch_bounds__(256, 2)
void dconv_gemm(const float* __restrict__ x, float* __restrict__ out) {
    __shared__ __align__(16) float As[BK][BM];   // weights [kc][o]
    __shared__ __align__(16) float Bs[BK][BN];   // sampled [kc][p]
    __shared__ float sw[4][BN];
    __shared__ int   si[4][BN];

    const int t   = blockIdx.x;          // 0..511
    const int b   = t >> 6;
    const int ho  = t & 63;
    const int om0 = blockIdx.y * BM;

    const int tid = threadIdx.x;
    const int tx  = tid & 15;            // pixel group (4 px)
    const int ty  = tid >> 4;            // cout group (8 rows)

    float acc[8][4];
    #pragma unroll
    for (int i = 0; i < 8; i++)
        #pragma unroll
        for (int j = 0; j < 4; j++) acc[i][j] = 0.0f;

    const float* xb = x + (((size_t)b * C) << 12);   // batch base
    const int pbase = ho * 64;

    for (int k = 0; k < 9; k++) {
        // load bilinear metadata for the 64 pixels of this row
        {
            int j = tid >> 6;            // 0..3
            int p = tid & 63;
            int e = ((b*9 + k) << 12) + pbase + p;
            float w; int ii;
            switch (j) {
                case 0: w = g_mw0[e]; ii = g_mi0[e]; break;
                case 1: w = g_mw1[e]; ii = g_mi1[e]; break;
                case 2: w = g_mw2[e]; ii = g_mi2[e]; break;
                default: w = g_mw3[e]; ii = g_mi3[e]; break;
            }
            sw[j][p] = w;
            si[j][p] = ii;
        }
        __syncthreads();

        for (int c0 = 0; c0 < C; c0 += BK) {
            // --- load A tile (transposed weights), coalesced ---
            #pragma unroll
            for (int i = 0; i < 4; i++) {
                int idx = tid + i * 256;            // 0..1023
                int kc  = idx >> 7;
                int m   = idx & 127;
                As[kc][m] = g_wt[(((k << 8) + c0 + kc) << 8) + om0 + m];
            }
            // --- build B tile: bilinear gather from x ---
            #pragma unroll
            for (int i = 0; i < 2; i++) {
                int idx = tid + i * 256;            // 0..511
                int kc  = idx >> 6;
                int p   = idx & 63;
                const float* xp = xb + ((size_t)(c0 + kc) << 12);
                float s = sw[0][p] * xp[si[0][p]]
                        + sw[1][p] * xp[si[1][p]]
                        + sw[2][p] * xp[si[2][p]]
                        + sw[3][p] * xp[si[3][p]];
                Bs[kc][p] = s;
            }
            __syncthreads();

            // --- compute ---
            #pragma unroll
            for (int kc = 0; kc < BK; kc++) {
                float4 a0 = *(const float4*)&As[kc][ty * 8];
                float4 a1 = *(const float4*)&As[kc][ty * 8 + 4];
                float4 bv = *(const float4*)&Bs[kc][tx * 4];
                float a[8] = {a0.x, a0.y, a0.z, a0.w, a1.x, a1.y, a1.z, a1.w};
                float bb[4] = {bv.x, bv.y, bv.z, bv.w};
                #pragma unroll
                for (int i = 0; i < 8; i++)
                    #pragma unroll
                    for (int j = 0; j < 4; j++)
                        acc[i][j] = fmaf(a[i], bb[j], acc[i][j]);
            }
            __syncthreads();
        }
    }

    // epilogue: out[((b*COUT + o)*64 + ho)*64 + wo]
    #pragma unroll
    for (int i = 0; i < 8; i++) {
        int o = om0 + ty * 8 + i;
        float* rowp = out + ((((size_t)b * COUT + o) * 64 + ho) << 6);
        float4 v = make_float4(acc[i][0], acc[i][1], acc[i][2], acc[i][3]);
        *(float4*)&rowp[tx * 4] = v;
    }
}

// ---------------------------------------------------------------------------
extern "C" void kernel_launch(void* const* d_in, const int* in_sizes, int n_in,
                              void* d_out, int out_size) {
    const float* x   = (const float*)d_in[0];
    const float* off = (const float*)d_in[1];
    const float* w   = (const float*)d_in[2];
    float* out = (float*)d_out;

    wtranspose_kernel<<<(K2*C*COUT + 255) / 256, 256>>>(w);
    meta_kernel<<<(BB*K2*PLANE + 255) / 256, 256>>>(off);

    dim3 grid(NPIX / BN, COUT / BM);
    dconv_gemm<<<grid, 256>>>(x, out);
}

// round 3
// speedup vs baseline: 1.9992x; 1.9992x over previous
#include <cuda_runtime.h>
#include <cstdint>

// Problem constants
#define BB   8
#define C    256
#define HH   64
#define WW   64
#define K2   9
#define COUT 256
#define PLANE (HH*WW)      // 4096
#define NPIX  (BB*PLANE)   // 32768
#define KJ   2304          // C*K2 (GEMM K per pass); 3 passes total

// ---------------------------------------------------------------------------
// Static device scratch
// ---------------------------------------------------------------------------
__device__ float g_mw0[BB*K2*PLANE];
__device__ float g_mw1[BB*K2*PLANE];
__device__ float g_mw2[BB*K2*PLANE];
__device__ float g_mw3[BB*K2*PLANE];
__device__ int   g_mi0[BB*K2*PLANE];
__device__ int   g_mi1[BB*K2*PLANE];
__device__ int   g_mi2[BB*K2*PLANE];
__device__ int   g_mi3[BB*K2*PLANE];

// Weights, bf16, 3 passes: [pass][o][j]   j = k9*256 + c
__device__ __align__(16) unsigned short g_A[3 * COUT * KJ];
// im2col sampled matrix, bf16 hi/lo planes: [p][j]
__device__ __align__(16) unsigned short g_Bhi[(size_t)NPIX * KJ];
__device__ __align__(16) unsigned short g_Blo[(size_t)NPIX * KJ];

// ---------------------------------------------------------------------------
// fp32 -> bf16 hi/lo split (round-to-nearest-even)
// ---------------------------------------------------------------------------
__device__ __forceinline__ void bsplit(float v, unsigned &h, unsigned &l) {
    unsigned u = __float_as_uint(v);
    unsigned r = (u + 0x7FFFu + ((u >> 16) & 1u)) & 0xFFFF0000u;
    h = r >> 16;
    float d = v - __uint_as_float(r);          // exact
    unsigned ud = __float_as_uint(d);
    l = (ud + 0x7FFFu + ((ud >> 16) & 1u)) >> 16;
}

// ---------------------------------------------------------------------------
// Kernel 1: weight prep
// ---------------------------------------------------------------------------
__global__ void aprep_kernel(const float* __restrict__ w) {
    int idx = blockIdx.x * 256 + threadIdx.x;    // o*KJ + j
    if (idx >= COUT * KJ) return;
    int o = idx / KJ;
    int j = idx - o * KJ;
    int c = j & 255, k9 = j >> 8;
    float v = w[((o << 8) + c) * 9 + k9];
    unsigned h, l; bsplit(v, h, l);
    g_A[idx]              = (unsigned short)h;   // pass0: A=hi (x B=hi)
    g_A[COUT*KJ + idx]    = (unsigned short)l;   // pass1: A=lo (x B=hi)
    g_A[2*COUT*KJ + idx]  = (unsigned short)h;   // pass2: A=hi (x B=lo)
}

// ---------------------------------------------------------------------------
// Kernel 2: bilinear metadata
// ---------------------------------------------------------------------------
__global__ void meta_kernel(const float* __restrict__ off) {
    int e = blockIdx.x * 256 + threadIdx.x;
    if (e >= BB*K2*PLANE) return;
    int p  = e & (PLANE - 1);
    int bk = e >> 12;
    int k  = bk % 9;
    int b  = bk / 9;
    int ho = p >> 6;
    int wo = p & 63;

    float dy = off[((size_t)(b*18 + 2*k    ) << 12) + p];
    float dx = off[((size_t)(b*18 + 2*k + 1) << 12) + p];

    float py = (float)(ho - 1 + (k / 3)) + dy;
    float px = (float)(wo - 1 + (k % 3)) + dx;

    float y0f = floorf(py), x0f = floorf(px);
    float fy = py - y0f, fx = px - x0f;
    int   y0 = (int)y0f,  x0 = (int)x0f;

    float wy[2] = {1.0f - fy, fy};
    float wx[2] = {1.0f - fx, fx};
    int   ys[2] = {y0, y0 + 1};
    int   xs[2] = {x0, x0 + 1};

    float mw[4]; int mi[4];
    #pragma unroll
    for (int jy = 0; jy < 2; jy++)
        #pragma unroll
        for (int jx = 0; jx < 2; jx++) {
            int jj = jy*2 + jx;
            int cy = ys[jy], cx = xs[jx];
            bool valid = (cy >= 0) && (cy < HH) && (cx >= 0) && (cx < WW);
            float wgt = valid ? wy[jy] * wx[jx] : 0.0f;
            int iy = min(max(cy, 0), HH - 1);
            int ix = min(max(cx, 0), WW - 1);
            mw[jj] = wgt;
            mi[jj] = iy * WW + ix;
        }
    g_mw0[e] = mw[0]; g_mw1[e] = mw[1]; g_mw2[e] = mw[2]; g_mw3[e] = mw[3];
    g_mi0[e] = mi[0]; g_mi1[e] = mi[1]; g_mi2[e] = mi[2]; g_mi3[e] = mi[3];
}

// ---------------------------------------------------------------------------
// Kernel 3: im2col gather -> bf16 hi/lo planes
// ---------------------------------------------------------------------------
__global__ __launch_bounds__(256)
void gather_kernel(const float* __restrict__ x) {
    int bid = blockIdx.x;
    int b = bid >> 6, ho = bid & 63;
    int tid = threadIdx.x;
    int p_l = tid & 63, q = tid >> 6;
    const float* xk = x + ((size_t)b << 20);
    int pg = (b << 12) + (ho << 6) + p_l;
    size_t prow = (size_t)pg * KJ;

    for (int k9 = 0; k9 < 9; k9++) {
        int e = ((b*9 + k9) << 12) + (ho << 6) + p_l;
        float w0 = g_mw0[e], w1 = g_mw1[e], w2 = g_mw2[e], w3 = g_mw3[e];
        int   i0 = g_mi0[e], i1 = g_mi1[e], i2 = g_mi2[e], i3 = g_mi3[e];

        for (int half = 0; half < 2; half++) {
            int c0 = (q << 6) + (half << 5);
            unsigned hp[16], lp[16];
            #pragma unroll
            for (int cp = 0; cp < 16; cp++) {
                const float* xp0 = xk + ((size_t)(c0 + 2*cp) << 12);
                const float* xp1 = xp0 + 4096;
                float v0 = w0*xp0[i0] + w1*xp0[i1] + w2*xp0[i2] + w3*xp0[i3];
                float v1 = w0*xp1[i0] + w1*xp1[i1] + w2*xp1[i2] + w3*xp1[i3];
                unsigned h0, l0, h1, l1;
                bsplit(v0, h0, l0);
                bsplit(v1, h1, l1);
                hp[cp] = h0 | (h1 << 16);
                lp[cp] = l0 | (l1 << 16);
            }
            size_t di = prow + (k9 << 8) + c0;
            uint4* dh = (uint4*)(g_Bhi + di);
            uint4* dl = (uint4*)(g_Blo + di);
            #pragma unroll
            for (int k = 0; k < 4; k++) {
                dh[k] = make_uint4(hp[4*k], hp[4*k+1], hp[4*k+2], hp[4*k+3]);
                dl[k] = make_uint4(lp[4*k], lp[4*k+1], lp[4*k+2], lp[4*k+3]);
            }
        }
    }
}

// ---------------------------------------------------------------------------
// Kernel 4: warp-MMA bf16 GEMM  D[o,p] = sum over 3 passes, K=2304 each
//   CTA tile 128x128, 8 warps (2 M x 4 N), warp tile 64x32, BK=64,
//   3-stage cp.async pipeline, SW128-swizzled smem, ldmatrix fragments.
// ---------------------------------------------------------------------------
#define SWZ(x) ((x) ^ (((x) >> 3) & 0x70))
#define NST    108                     // 3 passes * 36 stages (BK=64)
#define STAGE_BYTES 32768              // 16KB A + 16KB B
#define SM_TOTAL (3 * STAGE_BYTES)     // 96 KB

static __device__ __forceinline__ uint32_t smem_u32(const void* p) {
    uint32_t a;
    asm("{ .reg .u64 t; cvta.to.shared.u64 t, %1; cvt.u32.u64 %0, t; }"
        : "=r"(a) : "l"(p));
    return a;
}
static __device__ __forceinline__ void cp16(uint32_t dst, const void* src) {
    asm volatile("cp.async.cg.shared.global [%0], [%1], 16;\n"
                 :: "r"(dst), "l"(src));
}
#define LDSM4(r0, r1, r2, r3, a)                                              \
    asm volatile("ldmatrix.sync.aligned.m8n8.x4.shared.b16 {%0,%1,%2,%3}, [%4];" \
                 : "=r"(r0), "=r"(r1), "=r"(r2), "=r"(r3) : "r"(a))
#define MMA16816(d, a0, a1, a2, a3, b0, b1)                                   \
    asm volatile("mma.sync.aligned.m16n8k16.row.col.f32.bf16.bf16.f32 "       \
                 "{%0,%1,%2,%3}, {%4,%5,%6,%7}, {%8,%9}, {%0,%1,%2,%3};"      \
                 : "+f"((d)[0]), "+f"((d)[1]), "+f"((d)[2]), "+f"((d)[3])     \
                 : "r"(a0), "r"(a1), "r"(a2), "r"(a3), "r"(b0), "r"(b1))

static __device__ __forceinline__ void load_stage(int s, int buf, int tid,
                                                  uint32_t sb, int om0, int pt0) {
    int pass = (s >= 72) ? 2 : (s >= 36 ? 1 : 0);
    int js = (s - pass * 36) << 6;                 // k element offset
    const char* gA = (const char*)(g_A + ((size_t)(pass * COUT + om0) * KJ + js));
    const char* gB = (const char*)(((pass == 2) ? g_Blo : g_Bhi) +
                                   ((size_t)pt0 * KJ + js));
    uint32_t sA = sb + buf * STAGE_BYTES;
    uint32_t sB = sA + 16384;
    #pragma unroll
    for (int i = 0; i < 4; i++) {
        int id = tid + i * 256;                    // 0..1023
        int row = id >> 3;
        int kb  = (id & 7) << 4;                   // 16B chunk within 128B row
        cp16(sA + SWZ(row * 128 + kb), gA + (size_t)row * (KJ * 2) + kb);
        cp16(sB + SWZ(row * 128 + kb), gB + (size_t)row * (KJ * 2) + kb);
    }
    asm volatile("cp.async.commit_group;" ::: "memory");
}

__global__ __launch_bounds__(256, 2)
void dconv_gemm(float* __restrict__ out) {
    extern __shared__ char smem[];
    uint32_t sb = smem_u32(smem);
    int tid = threadIdx.x;
    int wid = tid >> 5, lid = tid & 31;
    const int om0 = blockIdx.y << 7;
    const int pt0 = blockIdx.x << 7;

    const int wm0 = (wid & 1) << 6;                // warp M base (0/64)
    const int wn0 = (wid >> 1) << 5;               // warp N base (0/32/64/96)

    float acc[4][4][4];
    #pragma unroll
    for (int i = 0; i < 4; i++)
        #pragma unroll
        for (int j = 0; j < 4; j++)
            #pragma unroll
            for (int r = 0; r < 4; r++) acc[i][j][r] = 0.0f;

    load_stage(0, 0, tid, sb, om0, pt0);
    load_stage(1, 1, tid, sb, om0, pt0);
    load_stage(2, 2, tid, sb, om0, pt0);

    int buf = 0;
    for (int s = 0; s < NST; s++) {
        if (s >= NST - 3)
            asm volatile("cp.async.wait_group 0;" ::: "memory");
        else
            asm volatile("cp.async.wait_group 2;" ::: "memory");
        __syncthreads();

        uint32_t sA = sb + buf * STAGE_BYTES;
        uint32_t sB = sA + 16384;
        int lr = lid & 15, lc = (lid >> 4) << 4;   // ldmatrix lane addressing

        #pragma unroll
        for (int ks = 0; ks < 4; ks++) {
            int kb = ks << 5;                      // 32B per k16 step
            uint32_t a[4][4];
            #pragma unroll
            for (int mt = 0; mt < 4; mt++) {
                uint32_t ad = sA + SWZ((wm0 + (mt << 4) + lr) * 128 + kb + lc);
                LDSM4(a[mt][0], a[mt][1], a[mt][2], a[mt][3], ad);
            }
            uint32_t br[2][4];
            #pragma unroll
            for (int bt = 0; bt < 2; bt++) {
                uint32_t bd = sB + SWZ((wn0 + (bt << 4) + lr) * 128 + kb + lc);
                LDSM4(br[bt][0], br[bt][1], br[bt][2], br[bt][3], bd);
            }
            #pragma unroll
            for (int mt = 0; mt < 4; mt++)
                #pragma unroll
                for (int n8 = 0; n8 < 4; n8++) {
                    int bt = n8 >> 1, nn = n8 & 1;
                    MMA16816(acc[mt][n8], a[mt][0], a[mt][1], a[mt][2], a[mt][3],
                             br[bt][nn], br[bt][nn + 2]);
                }
        }
        __syncthreads();
        if (s + 3 < NST)
            load_stage(s + 3, buf, tid, sb, om0, pt0);
        buf = (buf == 2) ? 0 : buf + 1;
    }

    // epilogue: out[((b*256 + o)*4096) + pin + col]
    int b = pt0 >> 12, pin = pt0 & 4095;
    #pragma unroll
    for (int mt = 0; mt < 4; mt++) {
        int o = om0 + wm0 + (mt << 4) + (lid >> 2);
        float* rp = out + (((size_t)((b << 8) + o)) << 12) + pin;
        #pragma unroll
        for (int n8 = 0; n8 < 4; n8++) {
            int col = wn0 + (n8 << 3) + ((lid & 3) << 1);
            *(float2*)(rp + col)            = make_float2(acc[mt][n8][0], acc[mt][n8][1]);
            *(float2*)(rp + (8 << 12) + col) = make_float2(acc[mt][n8][2], acc[mt][n8][3]);
        }
    }
}

// ---------------------------------------------------------------------------
extern "C" void kernel_launch(void* const* d_in, const int* in_sizes, int n_in,
                              void* d_out, int out_size) {
    const float* x   = (const float*)d_in[0];
    const float* off = (const float*)d_in[1];
    const float* w   = (const float*)d_in[2];
    float* out = (float*)d_out;

    cudaFuncSetAttribute(dconv_gemm,
                         cudaFuncAttributeMaxDynamicSharedMemorySize, SM_TOTAL);

    aprep_kernel<<<(COUT*KJ + 255) / 256, 256>>>(w);
    meta_kernel<<<(BB*K2*PLANE + 255) / 256, 256>>>(off);
    gather_kernel<<<BB * HH, 256>>>(x);

    dim3 grid(NPIX / 128, COUT / 128);
    dconv_gemm<<<grid, 256, SM_TOTAL>>>(out);
}

// round 4
// speedup vs baseline: 2.8290x; 1.4150x over previous
#include <cuda_runtime.h>
#include <cstdint>

// Problem constants
#define BB   8
#define C    256
#define HH   64
#define WW   64
#define K2   9
#define COUT 256
#define PLANE (HH*WW)      // 4096
#define NPIX  (BB*PLANE)   // 32768
#define KJ   2304          // C*K2

// ---------------------------------------------------------------------------
// Static device scratch
// ---------------------------------------------------------------------------
__device__ float g_mw0[BB*K2*PLANE];
__device__ float g_mw1[BB*K2*PLANE];
__device__ float g_mw2[BB*K2*PLANE];
__device__ float g_mw3[BB*K2*PLANE];
__device__ int   g_mi0[BB*K2*PLANE];
__device__ int   g_mi1[BB*K2*PLANE];
__device__ int   g_mi2[BB*K2*PLANE];
__device__ int   g_mi3[BB*K2*PLANE];

// Weights bf16, 2 planes: [plane][o][j]  (plane0=hi, plane1=lo), j = k9*256+c
__device__ __align__(16) unsigned short g_A[2 * COUT * KJ];

// ---------------------------------------------------------------------------
// fp32 -> bf16 hi/lo split (RNE) for weights
// ---------------------------------------------------------------------------
__device__ __forceinline__ void bsplit(float v, unsigned &h, unsigned &l) {
    unsigned u = __float_as_uint(v);
    unsigned r = (u + 0x7FFFu + ((u >> 16) & 1u)) & 0xFFFF0000u;
    h = r >> 16;
    float d = v - __uint_as_float(r);
    unsigned ud = __float_as_uint(d);
    l = (ud + 0x7FFFu + ((ud >> 16) & 1u)) >> 16;
}

// ---------------------------------------------------------------------------
// Kernel 1: weight prep
// ---------------------------------------------------------------------------
__global__ void aprep_kernel(const float* __restrict__ w) {
    int idx = blockIdx.x * 256 + threadIdx.x;    // o*KJ + j
    if (idx >= COUT * KJ) return;
    int o = idx / KJ;
    int j = idx - o * KJ;
    int c = j & 255, k9 = j >> 8;
    float v = w[((o << 8) + c) * 9 + k9];
    unsigned h, l; bsplit(v, h, l);
    g_A[idx]             = (unsigned short)h;
    g_A[COUT*KJ + idx]   = (unsigned short)l;
}

// ---------------------------------------------------------------------------
// Kernel 2: bilinear metadata
// ---------------------------------------------------------------------------
__global__ void meta_kernel(const float* __restrict__ off) {
    int e = blockIdx.x * 256 + threadIdx.x;
    if (e >= BB*K2*PLANE) return;
    int p  = e & (PLANE - 1);
    int bk = e >> 12;
    int k  = bk % 9;
    int b  = bk / 9;
    int ho = p >> 6;
    int wo = p & 63;

    float dy = off[((size_t)(b*18 + 2*k    ) << 12) + p];
    float dx = off[((size_t)(b*18 + 2*k + 1) << 12) + p];

    float py = (float)(ho - 1 + (k / 3)) + dy;
    float px = (float)(wo - 1 + (k % 3)) + dx;

    float y0f = floorf(py), x0f = floorf(px);
    float fy = py - y0f, fx = px - x0f;
    int   y0 = (int)y0f,  x0 = (int)x0f;

    float wy[2] = {1.0f - fy, fy};
    float wx[2] = {1.0f - fx, fx};
    int   ys[2] = {y0, y0 + 1};
    int   xs[2] = {x0, x0 + 1};

    float mw[4]; int mi[4];
    #pragma unroll
    for (int jy = 0; jy < 2; jy++)
        #pragma unroll
        for (int jx = 0; jx < 2; jx++) {
            int jj = jy*2 + jx;
            int cy = ys[jy], cx = xs[jx];
            bool valid = (cy >= 0) && (cy < HH) && (cx >= 0) && (cx < WW);
            float wgt = valid ? wy[jy] * wx[jx] : 0.0f;
            int iy = min(max(cy, 0), HH - 1);
            int ix = min(max(cx, 0), WW - 1);
            mw[jj] = wgt;
            mi[jj] = iy * WW + ix;
        }
    g_mw0[e] = mw[0]; g_mw1[e] = mw[1]; g_mw2[e] = mw[2]; g_mw3[e] = mw[3];
    g_mi0[e] = mi[0]; g_mi1[e] = mi[1]; g_mi2[e] = mi[2]; g_mi3[e] = mi[3];
}

// ---------------------------------------------------------------------------
// Kernel 3: fused gather + 3-pass split GEMM
//   CTA: M=256 (all Cout) x N=128 pixels. 512 threads (16 warps, 4Mx4N).
//   36 stages of BK=64 (one k9, 64 channels per stage).
//   smem/stage: Ah 32K | Al 32K | Bh 16K | Bl 16K = 96KB, double buffered.
// ---------------------------------------------------------------------------
#define SWZ(x) ((x) ^ (((x) >> 3) & 0x70))
#define NST2   36
#define STG    98304                   // 96 KB
#define SM_TOTAL (2 * STG)             // 192 KB

static __device__ __forceinline__ uint32_t smem_u32(const void* p) {
    uint32_t a;
    asm("{ .reg .u64 t; cvta.to.shared.u64 t, %1; cvt.u32.u64 %0, t; }"
        : "=r"(a) : "l"(p));
    return a;
}
static __device__ __forceinline__ void cp16(uint32_t dst, const void* src) {
    asm volatile("cp.async.cg.shared.global [%0], [%1], 16;\n"
                 :: "r"(dst), "l"(src));
}
#define LDSM4(r0, r1, r2, r3, a)                                              \
    asm volatile("ldmatrix.sync.aligned.m8n8.x4.shared.b16 {%0,%1,%2,%3}, [%4];" \
                 : "=r"(r0), "=r"(r1), "=r"(r2), "=r"(r3) : "r"(a))
#define MMA16816(d, a0, a1, a2, a3, b0, b1)                                   \
    asm volatile("mma.sync.aligned.m16n8k16.row.col.f32.bf16.bf16.f32 "       \
                 "{%0,%1,%2,%3}, {%4,%5,%6,%7}, {%8,%9}, {%0,%1,%2,%3};"      \
                 : "+f"((d)[0]), "+f"((d)[1]), "+f"((d)[2]), "+f"((d)[3])     \
                 : "r"(a0), "r"(a1), "r"(a2), "r"(a3), "r"(b0), "r"(b1))
#define STS128(a, v)                                                          \
    asm volatile("st.shared.v4.b32 [%0], {%1,%2,%3,%4};"                      \
                 :: "r"(a), "r"((v).x), "r"((v).y), "r"((v).z), "r"((v).w) : "memory")

// produce stage s into buffer (s&1): A via cp.async, B via gather+STS
static __device__ __forceinline__ void produce(int s, int tid, uint32_t sb,
                                               const float* __restrict__ x,
                                               int b, int pt0) {
    uint32_t base = sb + (s & 1) * STG;
    // ---- A tiles (hi, lo), 64 KB total, cp.async ----
    {
        const char* gA = (const char*)(g_A + (size_t)s * 64);
        #pragma unroll
        for (int pl = 0; pl < 2; pl++) {
            uint32_t dA = base + pl * 32768;
            const char* gp = gA + (size_t)pl * (COUT * KJ * 2);
            #pragma unroll
            for (int i = 0; i < 4; i++) {
                int id = tid + i * 512;            // 0..2047
                int row = id >> 3;
                int kb  = (id & 7) << 4;
                cp16(dA + SWZ(row * 128 + kb), gp + (size_t)row * (KJ * 2) + kb);
            }
        }
    }
    asm volatile("cp.async.commit_group;" ::: "memory");

    // ---- B tiles: bilinear gather, split to hi/lo, STS ----
    int k9 = s >> 2;
    int cb = (s & 3) << 6;
    int pxl = tid & 127;                           // local pixel
    int cg  = tid >> 7;                            // 0..3 -> 16 channels
    int e = ((b * 9 + k9) << 12) + ((pt0 & 4095) + pxl);
    float w0 = g_mw0[e], w1 = g_mw1[e], w2 = g_mw2[e], w3 = g_mw3[e];
    int   i0 = g_mi0[e], i1 = g_mi1[e], i2 = g_mi2[e], i3 = g_mi3[e];

    const float* xc = x + ((size_t)b << 20) + ((size_t)(cb + (cg << 4)) << 12);
    unsigned hi[8], lo[8];
    #pragma unroll
    for (int pr = 0; pr < 8; pr++) {
        const float* x0p = xc + ((size_t)(2 * pr) << 12);
        const float* x1p = x0p + 4096;
        float v0 = w0*x0p[i0] + w1*x0p[i1] + w2*x0p[i2] + w3*x0p[i3];
        float v1 = w0*x1p[i0] + w1*x1p[i1] + w2*x1p[i2] + w3*x1p[i3];
        unsigned u0 = __float_as_uint(v0);
        unsigned u1 = __float_as_uint(v1);
        unsigned r0 = u0 & 0xFFFF0000u;
        unsigned r1 = u1 & 0xFFFF0000u;
        float d0 = v0 - __uint_as_float(r0);       // exact
        float d1 = v1 - __uint_as_float(r1);
        hi[pr] = __byte_perm(u0, u1, 0x7632);
        lo[pr] = __byte_perm(__float_as_uint(d0), __float_as_uint(d1), 0x7632);
    }
    uint32_t sBh = base + 65536;
    uint32_t sBl = base + 81920;
    int boff = pxl * 128 + (cg << 5);
    uint4 h0 = make_uint4(hi[0], hi[1], hi[2], hi[3]);
    uint4 h1 = make_uint4(hi[4], hi[5], hi[6], hi[7]);
    uint4 l0 = make_uint4(lo[0], lo[1], lo[2], lo[3]);
    uint4 l1 = make_uint4(lo[4], lo[5], lo[6], lo[7]);
    STS128(sBh + SWZ(boff),      h0);
    STS128(sBh + SWZ(boff + 16), h1);
    STS128(sBl + SWZ(boff),      l0);
    STS128(sBl + SWZ(boff + 16), l1);
}

__global__ __launch_bounds__(512, 1)
void dconv_fused(const float* __restrict__ x, float* __restrict__ out) {
    extern __shared__ char smem[];
    uint32_t sb = smem_u32(smem);
    int tid = threadIdx.x;
    int wid = tid >> 5, lid = tid & 31;
    const int pt0 = blockIdx.x << 7;
    const int b = pt0 >> 12;

    const int wm0 = (wid & 3) << 6;                // 0/64/128/192
    const int wn0 = (wid >> 2) << 5;               // 0/32/64/96

    float acc[4][4][4];
    #pragma unroll
    for (int i = 0; i < 4; i++)
        #pragma unroll
        for (int j = 0; j < 4; j++)
            #pragma unroll
            for (int r = 0; r < 4; r++) acc[i][j][r] = 0.0f;

    produce(0, tid, sb, x, b, pt0);
    produce(1, tid, sb, x, b, pt0);

    for (int s = 0; s < NST2; s++) {
        if (s == NST2 - 1)
            asm volatile("cp.async.wait_group 0;" ::: "memory");
        else
            asm volatile("cp.async.wait_group 1;" ::: "memory");
        __syncthreads();

        uint32_t base = sb + (s & 1) * STG;
        uint32_t sAh = base, sAl = base + 32768;
        uint32_t sBh = base + 65536, sBl = base + 81920;
        int lr = lid & 15, lc = (lid >> 4) << 4;

        #pragma unroll
        for (int ks = 0; ks < 4; ks++) {
            int kb = ks << 5;
            uint32_t bh[2][4], bl[2][4];
            #pragma unroll
            for (int bt = 0; bt < 2; bt++) {
                uint32_t bd = sBh + SWZ((wn0 + (bt << 4) + lr) * 128 + kb + lc);
                LDSM4(bh[bt][0], bh[bt][1], bh[bt][2], bh[bt][3], bd);
            }
            #pragma unroll
            for (int bt = 0; bt < 2; bt++) {
                uint32_t bd = sBl + SWZ((wn0 + (bt << 4) + lr) * 128 + kb + lc);
                LDSM4(bl[bt][0], bl[bt][1], bl[bt][2], bl[bt][3], bd);
            }
            {
                uint32_t ah[4][4];
                #pragma unroll
                for (int mt = 0; mt < 4; mt++) {
                    uint32_t ad = sAh + SWZ((wm0 + (mt << 4) + lr) * 128 + kb + lc);
                    LDSM4(ah[mt][0], ah[mt][1], ah[mt][2], ah[mt][3], ad);
                }
                #pragma unroll
                for (int mt = 0; mt < 4; mt++)
                    #pragma unroll
                    for (int n8 = 0; n8 < 4; n8++) {
                        int bt = n8 >> 1, nn = n8 & 1;
                        MMA16816(acc[mt][n8], ah[mt][0], ah[mt][1], ah[mt][2], ah[mt][3],
                                 bh[bt][nn], bh[bt][nn + 2]);
                    }
                #pragma unroll
                for (int mt = 0; mt < 4; mt++)
                    #pragma unroll
                    for (int n8 = 0; n8 < 4; n8++) {
                        int bt = n8 >> 1, nn = n8 & 1;
                        MMA16816(acc[mt][n8], ah[mt][0], ah[mt][1], ah[mt][2], ah[mt][3],
                                 bl[bt][nn], bl[bt][nn + 2]);
                    }
            }
            {
                uint32_t al[4][4];
                #pragma unroll
                for (int mt = 0; mt < 4; mt++) {
                    uint32_t ad = sAl + SWZ((wm0 + (mt << 4) + lr) * 128 + kb + lc);
                    LDSM4(al[mt][0], al[mt][1], al[mt][2], al[mt][3], ad);
                }
                #pragma unroll
                for (int mt = 0; mt < 4; mt++)
                    #pragma unroll
                    for (int n8 = 0; n8 < 4; n8++) {
                        int bt = n8 >> 1, nn = n8 & 1;
                        MMA16816(acc[mt][n8], al[mt][0], al[mt][1], al[mt][2], al[mt][3],
                                 bh[bt][nn], bh[bt][nn + 2]);
                    }
            }
        }
        __syncthreads();
        if (s + 2 < NST2)
            produce(s + 2, tid, sb, x, b, pt0);
    }

    // epilogue: out[((b*256 + o) << 12) + pin + col]
    int pin = pt0 & 4095;
    #pragma unroll
    for (int mt = 0; mt < 4; mt++) {
        int o = wm0 + (mt << 4) + (lid >> 2);
        float* rp = out + (((size_t)((b << 8) + o)) << 12) + pin;
        #pragma unroll
        for (int n8 = 0; n8 < 4; n8++) {
            int col = wn0 + (n8 << 3) + ((lid & 3) << 1);
            *(float2*)(rp + col)             = make_float2(acc[mt][n8][0], acc[mt][n8][1]);
            *(float2*)(rp + (8 << 12) + col) = make_float2(acc[mt][n8][2], acc[mt][n8][3]);
        }
    }
}

// ---------------------------------------------------------------------------
extern "C" void kernel_launch(void* const* d_in, const int* in_sizes, int n_in,
                              void* d_out, int out_size) {
    const float* x   = (const float*)d_in[0];
    const float* off = (const float*)d_in[1];
    const float* w   = (const float*)d_in[2];
    float* out = (float*)d_out;

    cudaFuncSetAttribute(dconv_fused,
                         cudaFuncAttributeMaxDynamicSharedMemorySize, SM_TOTAL);

    aprep_kernel<<<(COUT*KJ + 255) / 256, 256>>>(w);
    meta_kernel<<<(BB*K2*PLANE + 255) / 256, 256>>>(off);

    dconv_fused<<<NPIX / 128, 512, SM_TOTAL>>>(x, out);
}